// round 9
// baseline (speedup 1.0000x reference)
#include <cuda_runtime.h>

#define B_    4
#define S_    2048
#define F_    64
#define HID_  256
#define D_    128
#define H_    8
#define DK_   16
#define NROWS (B_*S_)
#define BK_   128
#define KSPLIT 2
#define KLEN  (S_/KSPLIT)   // 1024 k rows per split
#define NTILE (KLEN/BK_)    // 8
#define QROWS 256           // q rows per attn block (2 per thread)

typedef unsigned long long u64;

// Scratch (device globals — no allocation allowed)
__device__ float g_q[NROWS*D_];
__device__ float g_k[NROWS*D_];
__device__ float g_v[NROWS*D_];
__device__ float g_pnum[KSPLIT*NROWS*D_];   // partial numerators
__device__ float g_pl  [KSPLIT*NROWS*H_];   // partial softmax denominators
__device__ float g_pmax[B_*16*D_];          // per-chunk max partials

__device__ __forceinline__ u64 pack2(float lo, float hi){
    u64 r; asm("mov.b64 %0,{%1,%2};" : "=l"(r) : "f"(lo), "f"(hi)); return r;
}
__device__ __forceinline__ void unpack2(u64 v, float &lo, float &hi){
    asm("mov.b64 {%0,%1},%2;" : "=f"(lo), "=f"(hi) : "l"(v));
}
__device__ __forceinline__ u64 fma2(u64 a, u64 b, u64 c){
    u64 d; asm("fma.rn.f32x2 %0,%1,%2,%3;" : "=l"(d) : "l"(a), "l"(b), "l"(c)); return d;
}
__device__ __forceinline__ u64 add2(u64 a, u64 b){
    u64 d; asm("add.rn.f32x2 %0,%1,%2;" : "=l"(d) : "l"(a), "l"(b)); return d;
}
__device__ __forceinline__ float ex2f(float x){
    float r; asm("ex2.approx.f32 %0,%1;" : "=f"(r) : "f"(x)); return r;
}
// horizontal sum of two packed pairs: (a.lo+a.hi)+(b.lo+b.hi)
__device__ __forceinline__ float hadd4(u64 a, u64 b){
    u64 s = add2(a, b);
    float lo, hi; unpack2(s, lo, hi);
    return lo + hi;
}

// ---------------------------------------------------------------------------
// Fused 2-layer MLP for Q,K,V in one launch: grid=(rows/32, 3).
// 128 threads, 32 rows/block, 2 columns per thread in both stages.
// Row-pairs packed in f32x2: acc lanes = (even row, odd row).
// ---------------------------------------------------------------------------
__global__ void __launch_bounds__(128) mlp3_kernel(
    const float* __restrict__ x,
    const float* __restrict__ qW1, const float* __restrict__ qb1,
    const float* __restrict__ qW2, const float* __restrict__ qb2,
    const float* __restrict__ kW1, const float* __restrict__ kb1,
    const float* __restrict__ kW2, const float* __restrict__ kb2,
    const float* __restrict__ vW1, const float* __restrict__ vb1,
    const float* __restrict__ vW2, const float* __restrict__ vb2)
{
    __shared__ u64 xs2[F_*17];    // [f][r2] packed (row 2r2, row 2r2+1), pad 17
    __shared__ u64 hs2[HID_*17];  // [j][r2] packed elu outputs

    const int sel  = blockIdx.y;
    const float* W1 = (sel == 0) ? qW1 : (sel == 1) ? kW1 : vW1;
    const float* b1 = (sel == 0) ? qb1 : (sel == 1) ? kb1 : vb1;
    const float* W2 = (sel == 0) ? qW2 : (sel == 1) ? kW2 : vW2;
    const float* b2 = (sel == 0) ? qb2 : (sel == 1) ? kb2 : vb2;
    float* out      = (sel == 0) ? g_q : (sel == 1) ? g_k : g_v;

    const int row0 = blockIdx.x * 32;
    const int t = threadIdx.x;

    float* xsf = (float*)xs2;
    for (int idx = t; idx < 32*F_; idx += 128){
        int r = idx >> 6, f = idx & 63;
        xsf[f*34 + r] = x[(size_t)(row0 + r)*F_ + f];
    }
    __syncthreads();

    // Stage 1: 2 columns per thread (t, t+128), 16 packed row-pairs each
    {
        const int c0 = t, c1 = t + 128;
        u64 acc[2][16];
        u64 bp0 = pack2(b1[c0], b1[c0]);
        u64 bp1 = pack2(b1[c1], b1[c1]);
        #pragma unroll
        for (int i = 0; i < 16; i++){ acc[0][i] = bp0; acc[1][i] = bp1; }

        #pragma unroll 4
        for (int f = 0; f < F_; f++){
            float w0 = W1[f*HID_ + c0];
            float w1 = W1[f*HID_ + c1];
            u64 w20 = pack2(w0, w0);
            u64 w21 = pack2(w1, w1);
            const u64* xr = &xs2[f*17];
            #pragma unroll
            for (int r2 = 0; r2 < 16; r2++){
                u64 xv = xr[r2];
                acc[0][r2] = fma2(xv, w20, acc[0][r2]);
                acc[1][r2] = fma2(xv, w21, acc[1][r2]);
            }
        }
        #pragma unroll
        for (int cc = 0; cc < 2; cc++){
            int c = (cc == 0) ? c0 : c1;
            #pragma unroll
            for (int r2 = 0; r2 < 16; r2++){
                float a, bv; unpack2(acc[cc][r2], a, bv);
                a  = (a  > 0.f) ? a  : (__expf(a)  - 1.f);   // elu
                bv = (bv > 0.f) ? bv : (__expf(bv) - 1.f);
                hs2[c*17 + r2] = pack2(a, bv);
            }
        }
    }
    __syncthreads();

    // Stage 2: half = t>>6 selects 8 row-pairs; 2 columns (cc, cc+64)
    {
        const int cc = t & 63;
        const int half = t >> 6;
        u64 acc2[2][8];
        u64 bp0 = pack2(b2[cc],      b2[cc]);
        u64 bp1 = pack2(b2[cc + 64], b2[cc + 64]);
        #pragma unroll
        for (int i = 0; i < 8; i++){ acc2[0][i] = bp0; acc2[1][i] = bp1; }

        #pragma unroll 4
        for (int j = 0; j < HID_; j++){
            float w0 = W2[j*D_ + cc];
            float w1 = W2[j*D_ + cc + 64];
            u64 w20 = pack2(w0, w0);
            u64 w21 = pack2(w1, w1);
            const u64* hr = &hs2[j*17 + half*8];
            #pragma unroll
            for (int rr = 0; rr < 8; rr++){
                u64 hv = hr[rr];
                acc2[0][rr] = fma2(hv, w20, acc2[0][rr]);
                acc2[1][rr] = fma2(hv, w21, acc2[1][rr]);
            }
        }
        #pragma unroll
        for (int rr = 0; rr < 8; rr++){
            int r2 = half*8 + rr;
            float lo0, hi0, lo1, hi1;
            unpack2(acc2[0][rr], lo0, hi0);
            unpack2(acc2[1][rr], lo1, hi1);
            out[(size_t)(row0 + 2*r2    )*D_ + cc]      = lo0;
            out[(size_t)(row0 + 2*r2 + 1)*D_ + cc]      = hi0;
            out[(size_t)(row0 + 2*r2    )*D_ + cc + 64] = lo1;
            out[(size_t)(row0 + 2*r2 + 1)*D_ + cc + 64] = hi1;
        }
    }
}

// ---------------------------------------------------------------------------
// Attention, split-K partial softmax, double-buffered k/v tiles.
// Block = (q-chunk of 256, (b,h), k-split of 1024). 128 threads, 2 q rows each.
// Single-j inner body (low register pressure, no spills at the 128-reg cap);
// latency hidden by 16 warps/SM. exp folded: q pre-scaled by 0.25*log2(e).
// ---------------------------------------------------------------------------
__global__ void __launch_bounds__(128, 4) attn_kernel()
{
    __shared__ u64 ks2[2][BK_*8];   // k rows as (k[2d],k[2d+1]) pairs, ping-pong
    __shared__ u64 vs2[2][BK_*8];

    const int bh = blockIdx.y;
    const int b = bh >> 3, h = bh & 7;
    const int split = blockIdx.z;
    const int hoff = h * DK_;
    const int qbase = blockIdx.x * QROWS;
    const int t = threadIdx.x;

    const float* qg = g_q + (size_t)b*S_*D_ + hoff;
    const float* kg = g_k + (size_t)b*S_*D_ + hoff;
    const float* vg = g_v + (size_t)b*S_*D_ + hoff;

    // 2 q rows; fold 1/sqrt(DK)=0.25 and log2(e) so softmax is raw ex2
    const float SC = 0.25f * 1.44269504088896f;
    u64 q2[2][8];
    #pragma unroll
    for (int r = 0; r < 2; r++){
        const float* qr = qg + (size_t)(qbase + t*2 + r)*D_;
        #pragma unroll
        for (int d2 = 0; d2 < 8; d2++)
            q2[r][d2] = pack2(qr[2*d2]*SC, qr[2*d2+1]*SC);
    }

    u64 acc[2][8];
    #pragma unroll
    for (int r = 0; r < 2; r++)
        #pragma unroll
        for (int d2 = 0; d2 < 8; d2++) acc[r][d2] = 0ULL;
    float lsum0 = 0.f, lsum1 = 0.f;

    const int k0 = split * KLEN;

    // Prefill tile 0
    for (int idx = t; idx < BK_*8; idx += 128){
        int j = idx >> 3, d2 = idx & 7;
        ks2[0][idx] = ((const u64*)(kg + (size_t)(k0+j)*D_))[d2];
        vs2[0][idx] = ((const u64*)(vg + (size_t)(k0+j)*D_))[d2];
    }

    for (int tile = 0; tile < NTILE; tile++){
        __syncthreads();
        const int cur = tile & 1;
        if (tile + 1 < NTILE){
            const int kb = k0 + (tile+1)*BK_;
            for (int idx = t; idx < BK_*8; idx += 128){
                int j = idx >> 3, d2 = idx & 7;
                ks2[cur^1][idx] = ((const u64*)(kg + (size_t)(kb+j)*D_))[d2];
                vs2[cur^1][idx] = ((const u64*)(vg + (size_t)(kb+j)*D_))[d2];
            }
        }
        const u64* ks = ks2[cur];
        const u64* vs = vs2[cur];

        #pragma unroll 2
        for (int j = 0; j < BK_; j++){
            const u64* kj = &ks[j*8];
            // 4 independent half-split score chains (depth 4)
            u64 sA0=0,sB0=0,sC0=0,sD0=0;
            #pragma unroll
            for (int d2 = 0; d2 < 4; d2++){
                u64 kv = kj[d2];
                sA0 = fma2(q2[0][d2], kv, sA0);
                sC0 = fma2(q2[1][d2], kv, sC0);
            }
            #pragma unroll
            for (int d2 = 4; d2 < 8; d2++){
                u64 kv = kj[d2];
                sB0 = fma2(q2[0][d2], kv, sB0);
                sD0 = fma2(q2[1][d2], kv, sD0);
            }
            float p0 = ex2f(hadd4(sA0, sB0));   // row0
            float p1 = ex2f(hadd4(sC0, sD0));   // row1
            lsum0 += p0; lsum1 += p1;
            u64 pd0 = pack2(p0, p0), pd1 = pack2(p1, p1);
            const u64* vj = &vs[j*8];
            #pragma unroll
            for (int d2 = 0; d2 < 8; d2++){
                u64 vv = vj[d2];
                acc[0][d2] = fma2(pd0, vv, acc[0][d2]);
                acc[1][d2] = fma2(pd1, vv, acc[1][d2]);
            }
        }
    }

    // Write partials (numerator + denominator) for this split
    #pragma unroll
    for (int r = 0; r < 2; r++){
        int row = b*S_ + qbase + t*2 + r;
        g_pl[((size_t)split*NROWS + row)*H_ + h] = (r == 0) ? lsum0 : lsum1;
        u64* np = (u64*)(g_pnum + ((size_t)split*NROWS + row)*D_ + hoff);
        #pragma unroll
        for (int d2 = 0; d2 < 8; d2++) np[d2] = acc[r][d2];
    }
}

// ---------------------------------------------------------------------------
// Combine splits + max over sequence (fused). grid=(B, 16 chunks), 128 thr.
// ---------------------------------------------------------------------------
__global__ void __launch_bounds__(128) max_part_kernel()
{
    int b = blockIdx.x, ch = blockIdx.y, d = threadIdx.x;
    int h = d >> 4;
    float m = -3.402823466e38f;
    #pragma unroll 4
    for (int s = 0; s < 128; s++){
        int row = b*S_ + ch*128 + s;
        float num = 0.f, l = 0.f;
        #pragma unroll
        for (int sp = 0; sp < KSPLIT; sp++){
            num += g_pnum[((size_t)sp*NROWS + row)*D_ + d];
            l   += g_pl  [((size_t)sp*NROWS + row)*H_ + h];
        }
        m = fmaxf(m, num / l);
    }
    g_pmax[(b*16 + ch)*D_ + d] = m;
}

__global__ void __launch_bounds__(512) max_final_kernel(float* __restrict__ out)
{
    int t = threadIdx.x;            // 512 = B*D
    int b = t >> 7, d = t & 127;
    float m = g_pmax[(b*16)*D_ + d];
    #pragma unroll
    for (int c = 1; c < 16; c++) m = fmaxf(m, g_pmax[(b*16 + c)*D_ + d]);
    out[t] = m;
}

// ---------------------------------------------------------------------------
extern "C" void kernel_launch(void* const* d_in, const int* in_sizes, int n_in,
                              void* d_out, int out_size)
{
    const float* x   = (const float*)d_in[0];
    const float* qW1 = (const float*)d_in[1];
    const float* qb1 = (const float*)d_in[2];
    const float* qW2 = (const float*)d_in[3];
    const float* qb2 = (const float*)d_in[4];
    const float* kW1 = (const float*)d_in[5];
    const float* kb1 = (const float*)d_in[6];
    const float* kW2 = (const float*)d_in[7];
    const float* kb2 = (const float*)d_in[8];
    const float* vW1 = (const float*)d_in[9];
    const float* vb1 = (const float*)d_in[10];
    const float* vW2 = (const float*)d_in[11];
    const float* vb2 = (const float*)d_in[12];

    mlp3_kernel<<<dim3(NROWS/32, 3), 128>>>(x,
        qW1, qb1, qW2, qb2, kW1, kb1, kW2, kb2, vW1, vb1, vW2, vb2);

    attn_kernel<<<dim3(S_/QROWS, B_*H_, KSPLIT), 128>>>();

    max_part_kernel<<<dim3(B_, 16), 128>>>();
    max_final_kernel<<<1, 512>>>((float*)d_out);
}

// round 13
// speedup vs baseline: 2.1972x; 2.1972x over previous
#include <cuda_runtime.h>
#include <cuda_bf16.h>
#include <cstdint>

#define B_    4
#define S_    2048
#define F_    64
#define HID_  256
#define D_    128
#define H_    8
#define DK_   16
#define NROWS (B_*S_)
#define BH_   (B_*H_)
#define QT    64            // q rows per attn block
#define KC    64            // k chunk
#define NC    (S_/KC)       // 32 chunks

typedef unsigned long long u64;
typedef unsigned int u32;
typedef unsigned short u16;

// ------------------------------ device scratch ------------------------------
__device__ float g_q[NROWS*D_];
__device__ float g_k[NROWS*D_];
__device__ float g_v[NROWS*D_];
__device__ u32   g_qb[BH_*S_*8];        // bf16x2 pairs, prescaled q  [bh][s][8]
__device__ u32   g_kb[BH_*S_*8];        // bf16x2 pairs k             [bh][s][8]
__device__ u16   g_vthi[BH_*16*S_];     // v hi bf16, transposed [bh][d][s]
__device__ u16   g_vtlo[BH_*16*S_];     // v lo bf16, transposed [bh][d][s]
__device__ float g_vsum[BH_*16];        // exact fp32 column sums of v
__device__ float g_o[NROWS*D_];
__device__ float g_pmax[B_*16*D_];

// ------------------------------ helpers -------------------------------------
__device__ __forceinline__ u32 smem_u32(const void* p){
    u32 a; asm("{ .reg .u64 t; cvta.to.shared.u64 t, %1; cvt.u32.u64 %0, t; }"
               : "=r"(a) : "l"(p)); return a;
}
__device__ __forceinline__ float ex2f(float x){
    float r; asm("ex2.approx.f32 %0,%1;" : "=f"(r) : "f"(x)); return r;
}
__device__ __forceinline__ u64 pack2(float lo, float hi){
    u64 r; asm("mov.b64 %0,{%1,%2};" : "=l"(r) : "f"(lo), "f"(hi)); return r;
}
__device__ __forceinline__ void unpack2(u64 v, float &lo, float &hi){
    asm("mov.b64 {%0,%1},%2;" : "=f"(lo), "=f"(hi) : "l"(v));
}
__device__ __forceinline__ u64 fma2(u64 a, u64 b, u64 c){
    u64 d; asm("fma.rn.f32x2 %0,%1,%2,%3;" : "=l"(d) : "l"(a), "l"(b), "l"(c)); return d;
}
// pack two f32 -> bf16x2 (lo = first arg)
__device__ __forceinline__ u32 bf2(float lo, float hi){
    u32 r; asm("cvt.rn.satfinite.bf16x2.f32 %0, %1, %2;" : "=r"(r) : "f"(hi), "f"(lo));
    return r;
}
// m16n8k16 bf16 MMA, fp32 accum (portable sm_80+ HMMA)
__device__ __forceinline__ void mma16816(float c[4], const u32 a[4], const u32 b0, const u32 b1){
    asm volatile("mma.sync.aligned.m16n8k16.row.col.f32.bf16.bf16.f32 "
        "{%0,%1,%2,%3}, {%4,%5,%6,%7}, {%8,%9}, {%0,%1,%2,%3};"
        : "+f"(c[0]), "+f"(c[1]), "+f"(c[2]), "+f"(c[3])
        : "r"(a[0]), "r"(a[1]), "r"(a[2]), "r"(a[3]), "r"(b0), "r"(b1));
}
__device__ __forceinline__ void cp16(u32 dst, const void* src){
    asm volatile("cp.async.ca.shared.global [%0], [%1], 16;" :: "r"(dst), "l"(src));
}
#define CP_COMMIT() asm volatile("cp.async.commit_group;" ::: "memory")
#define CP_WAIT1()  asm volatile("cp.async.wait_group 1;" ::: "memory")
#define CP_WAIT0()  asm volatile("cp.async.wait_group 0;" ::: "memory")

// ---------------------------------------------------------------------------
// Fused 2-layer MLP for Q,K,V (scalar f32x2; unchanged from best-passing)
// ---------------------------------------------------------------------------
__global__ void __launch_bounds__(128) mlp3_kernel(
    const float* __restrict__ x,
    const float* __restrict__ qW1, const float* __restrict__ qb1,
    const float* __restrict__ qW2, const float* __restrict__ qb2,
    const float* __restrict__ kW1, const float* __restrict__ kb1,
    const float* __restrict__ kW2, const float* __restrict__ kb2,
    const float* __restrict__ vW1, const float* __restrict__ vb1,
    const float* __restrict__ vW2, const float* __restrict__ vb2)
{
    __shared__ u64 xs2[F_*17];
    __shared__ u64 hs2[HID_*17];

    const int sel  = blockIdx.y;
    const float* W1 = (sel == 0) ? qW1 : (sel == 1) ? kW1 : vW1;
    const float* b1 = (sel == 0) ? qb1 : (sel == 1) ? kb1 : vb1;
    const float* W2 = (sel == 0) ? qW2 : (sel == 1) ? kW2 : vW2;
    const float* b2 = (sel == 0) ? qb2 : (sel == 1) ? kb2 : vb2;
    float* out      = (sel == 0) ? g_q : (sel == 1) ? g_k : g_v;

    const int row0 = blockIdx.x * 32;
    const int t = threadIdx.x;

    float* xsf = (float*)xs2;
    for (int idx = t; idx < 32*F_; idx += 128){
        int r = idx >> 6, f = idx & 63;
        xsf[f*34 + r] = x[(size_t)(row0 + r)*F_ + f];
    }
    __syncthreads();

    {
        const int c0 = t, c1 = t + 128;
        u64 acc[2][16];
        u64 bp0 = pack2(b1[c0], b1[c0]);
        u64 bp1 = pack2(b1[c1], b1[c1]);
        #pragma unroll
        for (int i = 0; i < 16; i++){ acc[0][i] = bp0; acc[1][i] = bp1; }

        #pragma unroll 4
        for (int f = 0; f < F_; f++){
            float w0 = W1[f*HID_ + c0];
            float w1 = W1[f*HID_ + c1];
            u64 w20 = pack2(w0, w0);
            u64 w21 = pack2(w1, w1);
            const u64* xr = &xs2[f*17];
            #pragma unroll
            for (int r2 = 0; r2 < 16; r2++){
                u64 xv = xr[r2];
                acc[0][r2] = fma2(xv, w20, acc[0][r2]);
                acc[1][r2] = fma2(xv, w21, acc[1][r2]);
            }
        }
        #pragma unroll
        for (int cc = 0; cc < 2; cc++){
            int c = (cc == 0) ? c0 : c1;
            #pragma unroll
            for (int r2 = 0; r2 < 16; r2++){
                float a, bv; unpack2(acc[cc][r2], a, bv);
                a  = (a  > 0.f) ? a  : (__expf(a)  - 1.f);
                bv = (bv > 0.f) ? bv : (__expf(bv) - 1.f);
                hs2[c*17 + r2] = pack2(a, bv);
            }
        }
    }
    __syncthreads();

    {
        const int cc = t & 63;
        const int half = t >> 6;
        u64 acc2[2][8];
        u64 bp0 = pack2(b2[cc],      b2[cc]);
        u64 bp1 = pack2(b2[cc + 64], b2[cc + 64]);
        #pragma unroll
        for (int i = 0; i < 8; i++){ acc2[0][i] = bp0; acc2[1][i] = bp1; }

        #pragma unroll 4
        for (int j = 0; j < HID_; j++){
            float w0 = W2[j*D_ + cc];
            float w1 = W2[j*D_ + cc + 64];
            u64 w20 = pack2(w0, w0);
            u64 w21 = pack2(w1, w1);
            const u64* hr = &hs2[j*17 + half*8];
            #pragma unroll
            for (int rr = 0; rr < 8; rr++){
                u64 hv = hr[rr];
                acc2[0][rr] = fma2(hv, w20, acc2[0][rr]);
                acc2[1][rr] = fma2(hv, w21, acc2[1][rr]);
            }
        }
        #pragma unroll
        for (int rr = 0; rr < 8; rr++){
            int r2 = half*8 + rr;
            float lo0, hi0, lo1, hi1;
            unpack2(acc2[0][rr], lo0, hi0);
            unpack2(acc2[1][rr], lo1, hi1);
            out[(size_t)(row0 + 2*r2    )*D_ + cc]      = lo0;
            out[(size_t)(row0 + 2*r2 + 1)*D_ + cc]      = hi0;
            out[(size_t)(row0 + 2*r2    )*D_ + cc + 64] = lo1;
            out[(size_t)(row0 + 2*r2 + 1)*D_ + cc + 64] = hi1;
        }
    }
}

// ---------------------------------------------------------------------------
// Convert: q -> bf16 prescaled pairs, k -> bf16 pairs, v -> transposed hi/lo
// ---------------------------------------------------------------------------
__global__ void __launch_bounds__(128) convert_kernel()
{
    const int t = threadIdx.x;
    const int row = blockIdx.x*128 + t;
    const int h = blockIdx.y;
    const int b = row >> 11, s = row & 2047;
    const int bh = b*H_ + h;
    const float SC = 0.25f * 1.44269504088896f;

    const float* qp = g_q + (size_t)row*D_ + h*DK_;
    const float* kp = g_k + (size_t)row*D_ + h*DK_;
    const float* vp = g_v + (size_t)row*D_ + h*DK_;

    u32* qo = g_qb + ((size_t)bh*S_ + s)*8;
    u32* ko = g_kb + ((size_t)bh*S_ + s)*8;
    #pragma unroll
    for (int i = 0; i < 8; i++){
        __nv_bfloat162 qv = __floats2bfloat162_rn(qp[2*i]*SC, qp[2*i+1]*SC);
        qo[i] = *reinterpret_cast<u32*>(&qv);
        __nv_bfloat162 kv = __floats2bfloat162_rn(kp[2*i], kp[2*i+1]);
        ko[i] = *reinterpret_cast<u32*>(&kv);
    }
    #pragma unroll
    for (int d = 0; d < DK_; d++){
        float v = vp[d];
        __nv_bfloat16 hb = __float2bfloat16(v);
        float hf = __bfloat162float(hb);
        __nv_bfloat16 lb = __float2bfloat16(v - hf);
        g_vthi[((size_t)bh*16 + d)*S_ + s] = *reinterpret_cast<u16*>(&hb);
        g_vtlo[((size_t)bh*16 + d)*S_ + s] = *reinterpret_cast<u16*>(&lb);
    }
}

// exact fp32 column sums of v per (b,h)
__global__ void __launch_bounds__(128) vsum_kernel()
{
    __shared__ float red[128];
    const int bh = blockIdx.x;
    const int b = bh >> 3, h = bh & 7;
    const int t = threadIdx.x;
    const int d = t & 15, part = t >> 4;
    float s = 0.f;
    for (int i = 0; i < 256; i++){
        int row = b*S_ + part*256 + i;
        s += g_v[(size_t)row*D_ + h*DK_ + d];
    }
    red[t] = s;
    __syncthreads();
    if (t < 16){
        float m = 0.f;
        #pragma unroll
        for (int p = 0; p < 8; p++) m += red[p*16 + t];
        g_vsum[bh*16 + d] = m;
    }
}

// ---------------------------------------------------------------------------
// Attention via portable mma.sync (bf16 HMMA, fp32 accum).
// grid (S/QT, BH_), 128 threads = 4 warps, warp owns 16 q rows.
// delta = 2^s - 1 built in registers (C->A fragment maps 1:1), V split hi/lo.
// out = (vsum + delta.V) / (S + sum(delta)); cp.async double-buffered K/Vt.
// ---------------------------------------------------------------------------
__global__ void __launch_bounds__(128) attn_mma_kernel()
{
    __shared__ __align__(16) u32 kbuf[2][KC*8];     // [s][8]  (dim pairs)
    __shared__ __align__(16) u32 vhbuf[2][16*36];   // [d][36] (s pairs, padded)
    __shared__ __align__(16) u32 vlbuf[2][16*36];

    const int t = threadIdx.x, wid = t >> 5, lane = t & 31;
    const int g = lane >> 2, tig = lane & 3;
    const int bh = blockIdx.y, b = bh >> 3, h = bh & 7;
    const int qbase = blockIdx.x * QT;

    // persistent Q fragment (A: m16k16)
    u32 qa[4];
    {
        const u32* qg = g_qb + ((size_t)bh*S_ + qbase + wid*16)*8;
        qa[0] = qg[g*8 + tig];
        qa[1] = qg[(g+8)*8 + tig];
        qa[2] = qg[g*8 + tig + 4];
        qa[3] = qg[(g+8)*8 + tig + 4];
    }

    float o0[4] = {0.f,0.f,0.f,0.f};    // dims 0-7
    float o1[4] = {0.f,0.f,0.f,0.f};    // dims 8-15
    float lg = 0.f, lg8 = 0.f;

    const char* kgl = (const char*)(g_kb + (size_t)bh*S_*8);
    const char* vhg = (const char*)(g_vthi + (size_t)bh*16*S_);
    const char* vlg = (const char*)(g_vtlo + (size_t)bh*16*S_);

    const u32 kS  = smem_u32(kbuf);
    const u32 vhS = smem_u32(vhbuf);
    const u32 vlS = smem_u32(vlbuf);
    const int cd = t >> 3, cj = t & 7;

    // prefetch chunk 0
    {
        const int s0 = 0;
        cp16(kS + t*16, kgl + (size_t)s0*32 + t*16);
        cp16(vhS + cd*144 + cj*16, vhg + ((size_t)cd*S_ + s0)*2 + cj*16);
        cp16(vlS + cd*144 + cj*16, vlg + ((size_t)cd*S_ + s0)*2 + cj*16);
        CP_COMMIT();
    }

    for (int c = 0; c < NC; c++){
        const int cur = c & 1;
        if (c + 1 < NC){
            const int nb = cur ^ 1;
            const int s0 = (c+1)*KC;
            cp16(kS + nb*2048 + t*16, kgl + (size_t)s0*32 + t*16);
            cp16(vhS + nb*2304 + cd*144 + cj*16, vhg + ((size_t)cd*S_ + s0)*2 + cj*16);
            cp16(vlS + nb*2304 + cd*144 + cj*16, vlg + ((size_t)cd*S_ + s0)*2 + cj*16);
            CP_COMMIT();
            CP_WAIT1();
        } else {
            CP_WAIT0();
        }
        __syncthreads();

        const u32* kb  = kbuf[cur];
        const u32* vhb = vhbuf[cur];
        const u32* vlb = vlbuf[cur];

        #pragma unroll
        for (int ss = 0; ss < 4; ss++){
            // scores: two n8 tiles over 16 k-positions
            float c0[4] = {0.f,0.f,0.f,0.f};
            float c1[4] = {0.f,0.f,0.f,0.f};
            {
                const u32* kr0 = &kb[(ss*16 + g)*8];
                mma16816(c0, qa, kr0[tig], kr0[tig+4]);
                const u32* kr1 = &kb[(ss*16 + 8 + g)*8];
                mma16816(c1, qa, kr1[tig], kr1[tig+4]);
            }
            // delta = 2^s - 1 (registers only; C layout == next A layout)
            float d00 = ex2f(c0[0]) - 1.f, d01 = ex2f(c0[1]) - 1.f;
            float d02 = ex2f(c0[2]) - 1.f, d03 = ex2f(c0[3]) - 1.f;
            float d10 = ex2f(c1[0]) - 1.f, d11 = ex2f(c1[1]) - 1.f;
            float d12 = ex2f(c1[2]) - 1.f, d13 = ex2f(c1[3]) - 1.f;
            lg  += (d00 + d01) + (d10 + d11);
            lg8 += (d02 + d03) + (d12 + d13);
            u32 pa[4];
            pa[0] = bf2(d00, d01);   // row g,   kpos 0-7 tile
            pa[1] = bf2(d02, d03);   // row g+8, kpos 0-7
            pa[2] = bf2(d10, d11);   // row g,   kpos 8-15
            pa[3] = bf2(d12, d13);   // row g+8, kpos 8-15
            // PV: dims 0-7 (o0), dims 8-15 (o1), V hi + lo
            const int vi = ss*8 + tig;
            mma16816(o0, pa, vhb[g*36 + vi],     vhb[g*36 + vi + 4]);
            mma16816(o1, pa, vhb[(g+8)*36 + vi], vhb[(g+8)*36 + vi + 4]);
            mma16816(o0, pa, vlb[g*36 + vi],     vlb[g*36 + vi + 4]);
            mma16816(o1, pa, vlb[(g+8)*36 + vi], vlb[(g+8)*36 + vi + 4]);
        }
        __syncthreads();
    }

    // reduce lsum over the 4 lanes sharing a row (tig bits = lane bits 0-1)
    lg  += __shfl_xor_sync(0xffffffffu, lg, 1);
    lg  += __shfl_xor_sync(0xffffffffu, lg, 2);
    lg8 += __shfl_xor_sync(0xffffffffu, lg8, 1);
    lg8 += __shfl_xor_sync(0xffffffffu, lg8, 2);

    const float inv0 = 1.f / ((float)S_ + lg);
    const float inv1 = 1.f / ((float)S_ + lg8);
    const int row0 = qbase + wid*16 + g;
    const float* vs = g_vsum + bh*16;
    float* op0 = g_o + ((size_t)(b*S_ + row0))*D_ + h*DK_;
    float* op1 = op0 + (size_t)8*D_;
    const int dlo = 2*tig, dhi = 2*tig + 8;
    op0[dlo]   = (vs[dlo]   + o0[0])*inv0;
    op0[dlo+1] = (vs[dlo+1] + o0[1])*inv0;
    op0[dhi]   = (vs[dhi]   + o1[0])*inv0;
    op0[dhi+1] = (vs[dhi+1] + o1[1])*inv0;
    op1[dlo]   = (vs[dlo]   + o0[2])*inv1;
    op1[dlo+1] = (vs[dlo+1] + o0[3])*inv1;
    op1[dhi]   = (vs[dhi]   + o1[2])*inv1;
    op1[dhi+1] = (vs[dhi+1] + o1[3])*inv1;
}

// ---------------------------------------------------------------------------
// Max over sequence
// ---------------------------------------------------------------------------
__global__ void __launch_bounds__(128) max_part_kernel()
{
    int b = blockIdx.x, ch = blockIdx.y, d = threadIdx.x;
    float m = -3.402823466e38f;
    #pragma unroll 4
    for (int s = 0; s < 128; s++){
        int row = b*S_ + ch*128 + s;
        m = fmaxf(m, g_o[(size_t)row*D_ + d]);
    }
    g_pmax[(b*16 + ch)*D_ + d] = m;
}

__global__ void __launch_bounds__(512) max_final_kernel(float* __restrict__ out)
{
    int t = threadIdx.x;
    int b = t >> 7, d = t & 127;
    float m = g_pmax[(b*16)*D_ + d];
    #pragma unroll
    for (int c = 1; c < 16; c++) m = fmaxf(m, g_pmax[(b*16 + c)*D_ + d]);
    out[t] = m;
}

// ---------------------------------------------------------------------------
extern "C" void kernel_launch(void* const* d_in, const int* in_sizes, int n_in,
                              void* d_out, int out_size)
{
    const float* x   = (const float*)d_in[0];
    const float* qW1 = (const float*)d_in[1];
    const float* qb1 = (const float*)d_in[2];
    const float* qW2 = (const float*)d_in[3];
    const float* qb2 = (const float*)d_in[4];
    const float* kW1 = (const float*)d_in[5];
    const float* kb1 = (const float*)d_in[6];
    const float* kW2 = (const float*)d_in[7];
    const float* kb2 = (const float*)d_in[8];
    const float* vW1 = (const float*)d_in[9];
    const float* vb1 = (const float*)d_in[10];
    const float* vW2 = (const float*)d_in[11];
    const float* vb2 = (const float*)d_in[12];

    mlp3_kernel<<<dim3(NROWS/32, 3), 128>>>(x,
        qW1, qb1, qW2, qb2, kW1, kb1, kW2, kb2, vW1, vb1, vW2, vb2);

    convert_kernel<<<dim3(NROWS/128, H_), 128>>>();
    vsum_kernel<<<BH_, 128>>>();

    attn_mma_kernel<<<dim3(S_/QT, BH_), 128>>>();

    max_part_kernel<<<dim3(B_, 16), 128>>>();
    max_final_kernel<<<1, 512>>>((float*)d_out);
}